// round 1
// baseline (speedup 1.0000x reference)
#include <cuda_runtime.h>
#include <cuda_bf16.h>
#include <cstdint>

// 21x21 circular box filter on (8,1,2048,2048) fp32.
// Separable: vertical running sum (global -> smem), horizontal running sum
// (smem -> regs), staged coalesced store.

#define H 2048
#define W 2048
#define NB 8
#define R 10              // half-width
#define KW (2*R + 1)      // 21
#define TX 128            // tile width  (x)
#define TY 64             // tile height (y)
#define VS 149            // vert smem row stride (TX + 2R = 148, +1 pad; 149%32=21, gcd(21,32)=1)
#define OS 129            // output staging stride (129%32=1 -> conflict free)
#define THREADS 512

__global__ __launch_bounds__(THREADS, 2)
void box_filter_kernel(const float* __restrict__ in, float* __restrict__ out)
{
    __shared__ float vert[TY * VS];   // 64*149*4 = 38,144 B (reused as output staging)

    const int t  = threadIdx.x;
    const int bx = blockIdx.x;        // x tile: 0..15
    const int by = blockIdx.y;        // y tile: 0..31
    const int bz = blockIdx.z;        // batch:  0..7

    const float* img  = in  + (size_t)bz * (size_t)(H * W);
    float*       outg = out + (size_t)bz * (size_t)(H * W);

    const int tileX = bx * TX;
    const int tileY = by * TY;

    // ---------------- Stage 1: vertical box sums (global -> smem) -------------
    // 148 columns (TX + 2R), each split into 2 vertical halves of 32 rows.
    // Threads 0..295 active. Lanes map to consecutive columns -> coalesced LDG.
    if (t < 2 * (TX + 2 * R)) {
        const int h = (t >= (TX + 2 * R)) ? 1 : 0;
        const int c = t - h * (TX + 2 * R);           // 0..147
        const int gx = (tileX + c - R) & (W - 1);     // wrapped global x
        const int y0 = tileY + h * (TY / 2) - R;      // first input row (may be <0)

        const float* colp = img + gx;

        float s = 0.0f;
        #pragma unroll
        for (int j = 0; j < KW; j++) {
            s += colp[((y0 + j) & (H - 1)) * W];
        }
        vert[(h * (TY / 2)) * VS + c] = s;

        #pragma unroll 4
        for (int i = 1; i < TY / 2; i++) {
            s += colp[((y0 + 2 * R + i) & (H - 1)) * W]
               - colp[((y0 + i - 1)    & (H - 1)) * W];
            vert[(h * (TY / 2) + i) * VS + c] = s;
        }
    }
    __syncthreads();

    // ---------------- Stage 2: horizontal box sums (smem -> regs) -------------
    // 64 rows x 8 segments of 16 outputs = 512 tasks.
    // Lanes within a warp hold consecutive r, same sg:
    //   addr = r*149 + sg*16 + i -> bank 21*r (+const) mod 32: conflict-free.
    const int r  = t & (TY - 1);      // 0..63
    const int sg = t >> 6;            // 0..7
    const int x0 = sg * 16;

    const float* vrow = vert + r * VS;

    float o[16];
    {
        float s = 0.0f;
        #pragma unroll
        for (int j = 0; j < KW; j++) s += vrow[x0 + j];
        o[0] = s;
        #pragma unroll
        for (int i = 1; i < 16; i++) {
            s += vrow[x0 + 2 * R + i] - vrow[x0 + i - 1];
            o[i] = s;
        }
    }
    __syncthreads();   // done reading vert; reuse buffer as staging

    // ---------------- Stage 3: stage + coalesced global store -----------------
    float* outs = vert;               // 64*129 = 8256 floats <= 64*149
    #pragma unroll
    for (int i = 0; i < 16; i++) {
        // lanes: consecutive r, same sg -> bank r mod 32: conflict-free
        outs[r * OS + x0 + i] = o[i];
    }
    __syncthreads();

    #pragma unroll
    for (int k = t; k < TX * TY; k += THREADS) {
        const int rr = k >> 7;        // /TX
        const int cc = k & (TX - 1);
        outg[(size_t)(tileY + rr) * W + tileX + cc] = outs[rr * OS + cc];
    }
}

extern "C" void kernel_launch(void* const* d_in, const int* in_sizes, int n_in,
                              void* d_out, int out_size)
{
    const float* x = (const float*)d_in[0];
    // d_in[1] is the all-ones (1,1,21,21) kernel: constant for this problem, unused.
    float* out = (float*)d_out;

    dim3 grid(W / TX, H / TY, NB);    // (16, 32, 8)
    box_filter_kernel<<<grid, THREADS>>>(x, out);
}

// round 2
// speedup vs baseline: 1.0003x; 1.0003x over previous
#include <cuda_runtime.h>
#include <cuda_bf16.h>
#include <cstdint>

// 21x21 circular box filter on (8,1,2048,2048) fp32, separable, single fused kernel.
// Phase 0: stream input tile (84 x 152) to SMEM with float4, all 512 threads (high MLP)
// Phase 1: vertical running box-sums SMEM->SMEM (thread per column)
// Phase 2: horizontal running box-sums SMEM->regs (thread per row-segment)
// Phase 3: stage in SMEM, vectorized coalesced stores.

#define H  2048
#define W  2048
#define NB 8
#define R  10
#define KW (2*R + 1)          // 21
#define TX 128
#define TY 64
#define IN_ROWS (TY + 2*R)    // 84
#define IN_STRIDE 152         // 148 used cols + align pad (x offset -12, float4 aligned)
#define VS 149                // vert stride: 149%32=21, coprime -> conflict-free in phase 2
#define OS 129                // staging stride
#define THREADS 512

#define SMEM_FLOATS (IN_ROWS*IN_STRIDE + TY*VS)   // 12768 + 9536 = 22304
#define SMEM_BYTES  (SMEM_FLOATS * 4)             // 89216

__global__ __launch_bounds__(THREADS, 2)
void box_filter_kernel(const float* __restrict__ in, float* __restrict__ out)
{
    extern __shared__ float sm[];
    float* inbuf = sm;                       // 84 x 152 (input tile, x offset -12)
    float* vert  = sm + IN_ROWS * IN_STRIDE; // 64 x 149 (vertical box sums)

    const int t  = threadIdx.x;
    const int bx = blockIdx.x;
    const int by = blockIdx.y;
    const int bz = blockIdx.z;

    const float* img  = in  + (size_t)bz * (size_t)(H * W);
    float*       outg = out + (size_t)bz * (size_t)(H * W);

    const int tileX = bx * TX;
    const int tileY = by * TY;

    // ---------------- Phase 0: stream tile to SMEM (float4, all threads) ------
    {
        const float4* img4   = reinterpret_cast<const float4*>(img);
        float4*       inbuf4 = reinterpret_cast<float4*>(inbuf);
        const int n4 = IN_ROWS * (IN_STRIDE / 4);          // 84*38 = 3192
        #pragma unroll 2
        for (int k = t; k < n4; k += THREADS) {
            const int row = k / (IN_STRIDE / 4);
            const int m   = k - row * (IN_STRIDE / 4);
            const int gy  = (tileY - R + row) & (H - 1);
            const int gx  = (tileX - 12 + 4 * m) & (W - 1); // 16B-aligned, wrap-safe
            inbuf4[k] = img4[(gy * W + gx) >> 2];
        }
    }
    __syncthreads();

    // ---------------- Phase 1: vertical running sums (SMEM -> SMEM) -----------
    // 148 columns x 2 row-halves of 32. Column c lives at inbuf col c+2.
    if (t < 2 * (TX + 2 * R)) {
        const int h  = (t >= (TX + 2 * R)) ? 1 : 0;
        const int c  = t - h * (TX + 2 * R);    // 0..147
        const int i0 = h * (TY / 2);
        const float* colp = inbuf + (c + 2);

        float s = 0.0f;
        #pragma unroll
        for (int j = 0; j < KW; j++) s += colp[(i0 + j) * IN_STRIDE];
        vert[i0 * VS + c] = s;

        #pragma unroll 4
        for (int i = 1; i < TY / 2; i++) {
            s += colp[(i0 + i + 2 * R) * IN_STRIDE]
               - colp[(i0 + i - 1)     * IN_STRIDE];
            vert[(i0 + i) * VS + c] = s;
        }
    }
    __syncthreads();

    // ---------------- Phase 2: horizontal running sums (SMEM -> regs) ---------
    const int r  = t & (TY - 1);   // 0..63
    const int sg = t >> 6;         // 0..7
    const int x0 = sg * 16;
    const float* vrow = vert + r * VS + x0;

    float o[16];
    {
        float s = 0.0f;
        #pragma unroll
        for (int j = 0; j < KW; j++) s += vrow[j];
        o[0] = s;
        #pragma unroll
        for (int i = 1; i < 16; i++) {
            s += vrow[2 * R + i] - vrow[i - 1];
            o[i] = s;
        }
    }

    // ---------------- Phase 3: stage (reuse inbuf) + vectorized store ---------
    float* outs = inbuf;           // 64 x 129, fits in inbuf region
    #pragma unroll
    for (int i = 0; i < 16; i++) {
        outs[r * OS + x0 + i] = o[i];   // lanes = consecutive r -> conflict-free
    }
    __syncthreads();

    {
        float4* outg4 = reinterpret_cast<float4*>(outg);
        const int n4 = TX * TY / 4;                 // 2048
        #pragma unroll
        for (int k = t; k < n4; k += THREADS) {
            const int rr = k >> 5;                  // / (TX/4)
            const int c4 = k & 31;
            float4 v;
            v.x = outs[rr * OS + 4 * c4 + 0];
            v.y = outs[rr * OS + 4 * c4 + 1];
            v.z = outs[rr * OS + 4 * c4 + 2];
            v.w = outs[rr * OS + 4 * c4 + 3];
            outg4[((size_t)(tileY + rr) * W + tileX + 4 * c4) >> 2] = v;
        }
    }
}

extern "C" void kernel_launch(void* const* d_in, const int* in_sizes, int n_in,
                              void* d_out, int out_size)
{
    const float* x = (const float*)d_in[0];
    float* out = (float*)d_out;

    cudaFuncSetAttribute(box_filter_kernel,
                         cudaFuncAttributeMaxDynamicSharedMemorySize, SMEM_BYTES);

    dim3 grid(W / TX, H / TY, NB);   // (16, 32, 8)
    box_filter_kernel<<<grid, THREADS, SMEM_BYTES>>>(x, out);
}

// round 3
// speedup vs baseline: 1.2247x; 1.2243x over previous
#include <cuda_runtime.h>
#include <cuda_bf16.h>
#include <cstdint>

// 21x21 circular box filter on (8,1,2048,2048) fp32, separable, fused.
// Occupancy-first variant: 256-thread CTAs, TY=32, 19KB smem, <=42 regs
// -> 6 CTAs/SM so load/compute phases of different CTAs overlap.

#define H  2048
#define W  2048
#define NB 8
#define R  10
#define KW (2*R + 1)        // 21
#define TX 128
#define TY 32
#define NC (TX + 2*R)       // 148 columns incl. halo
#define VS 149              // vert stride: 149%32=21, coprime with 32 -> conflict-free
#define OS 129              // staging stride (129%32=1)
#define THREADS 256

__global__ __launch_bounds__(THREADS, 6)
void box_filter_kernel(const float* __restrict__ in, float* __restrict__ out)
{
    __shared__ float vert[TY * VS];   // 32*149*4 = 19,072 B; reused as staging (32*129)

    const int t  = threadIdx.x;
    const int bx = blockIdx.x;
    const int by = blockIdx.y;
    const int bz = blockIdx.z;

    const float* img  = in  + (size_t)bz * (size_t)(H * W);
    float*       outg = out + (size_t)bz * (size_t)(H * W);

    const int tileX = bx * TX;
    const int tileY = by * TY;

    // ---------------- Phase A: vertical running sums (global -> smem) ---------
    // Thread per column (148 active). Lanes = consecutive columns -> coalesced.
    // Trailing-stream re-reads hit L1 (same address, 21 iters earlier).
    if (t < NC) {
        const int gx = (tileX + t - R) & (W - 1);
        const int y0 = tileY - R;
        const float* colp = img + gx;

        float s = 0.0f;
        #pragma unroll
        for (int j = 0; j < KW; j++) {
            s += colp[((y0 + j) & (H - 1)) * W];
        }
        vert[t] = s;

        #pragma unroll 4
        for (int i = 1; i < TY; i++) {
            s += colp[((y0 + 2 * R + i) & (H - 1)) * W]
               - colp[((y0 + i - 1)     & (H - 1)) * W];
            vert[i * VS + t] = s;
        }
    }
    __syncthreads();

    // ---------------- Phase B: horizontal running sums (smem -> regs) ---------
    // 32 rows x 8 segments of 16 outputs = 256 tasks. Warp lanes = consecutive
    // rows r; bank = (21*r + const) mod 32 -> conflict-free.
    const int r  = t & (TY - 1);     // 0..31
    const int sg = t >> 5;           // 0..7
    const int x0 = sg * 16;
    const float* vrow = vert + r * VS + x0;

    float o[16];
    {
        float s = 0.0f;
        #pragma unroll
        for (int j = 0; j < KW; j++) s += vrow[j];
        o[0] = s;
        #pragma unroll
        for (int i = 1; i < 16; i++) {
            s += vrow[2 * R + i] - vrow[i - 1];
            o[i] = s;
        }
    }
    __syncthreads();    // done reading vert; reuse as output staging

    // ---------------- Phase C: stage + vectorized coalesced store -------------
    float* outs = vert;              // 32 x 129 = 4128 floats <= 32*149
    #pragma unroll
    for (int i = 0; i < 16; i++) {
        outs[r * OS + x0 + i] = o[i];   // lanes = consecutive r -> conflict-free
    }
    __syncthreads();

    {
        float4* outg4 = reinterpret_cast<float4*>(outg);
        const int n4 = TX * TY / 4;             // 1024
        #pragma unroll
        for (int k = t; k < n4; k += THREADS) {
            const int rr = k >> 5;              // / (TX/4)
            const int c4 = k & 31;
            const float* p = outs + rr * OS + 4 * c4;
            float4 v;
            v.x = p[0]; v.y = p[1]; v.z = p[2]; v.w = p[3];
            outg4[((size_t)(tileY + rr) * W + tileX + 4 * c4) >> 2] = v;
        }
    }
}

extern "C" void kernel_launch(void* const* d_in, const int* in_sizes, int n_in,
                              void* d_out, int out_size)
{
    const float* x = (const float*)d_in[0];
    float* out = (float*)d_out;

    dim3 grid(W / TX, H / TY, NB);   // (16, 64, 8) = 8192 blocks
    box_filter_kernel<<<grid, THREADS>>>(x, out);
}

// round 4
// speedup vs baseline: 1.3137x; 1.0726x over previous
#include <cuda_runtime.h>
#include <cuda_bf16.h>
#include <cstdint>

// 21x21 circular box filter on (8,1,2048,2048) fp32, separable, fused.
// Phase A: vertical running box-sums global -> smem (thread per column)
// Phase B: horizontal box-sums via warp prefix scan (warp per row),
//          direct coalesced float4 stores. No staging phase, 1 barrier.

#define H  2048
#define W  2048
#define NB 8
#define R  10
#define KW (2*R + 1)        // 21
#define TX 128
#define TY 32
#define NC (TX + 2*R)       // 148 columns incl. halo
#define VS 152              // vert row stride (floats): 16B-aligned rows for LDS.128
#define THREADS 256

__global__ __launch_bounds__(THREADS, 6)
void box_filter_kernel(const float* __restrict__ in, float* __restrict__ out)
{
    __shared__ float vert[TY * VS];   // 32*152*4 = 19,456 B

    const int t  = threadIdx.x;
    const int bx = blockIdx.x;
    const int by = blockIdx.y;
    const int bz = blockIdx.z;

    const float* img  = in  + (size_t)bz * (size_t)(H * W);
    float*       outg = out + (size_t)bz * (size_t)(H * W);

    const int tileX = bx * TX;
    const int tileY = by * TY;

    // ---------------- Phase A: vertical running sums (global -> smem) ---------
    // Thread per halo column (148 active). Lanes = consecutive columns.
    if (t < NC) {
        const int gx = (tileX + t - R) & (W - 1);
        const int y0 = tileY - R;
        const float* colp = img + gx;

        float s = 0.0f;
        #pragma unroll
        for (int j = 0; j < KW; j++) {
            s += colp[((y0 + j) & (H - 1)) * W];
        }
        vert[t] = s;

        #pragma unroll 4
        for (int i = 1; i < TY; i++) {
            s += colp[((y0 + 2 * R + i) & (H - 1)) * W]
               - colp[((y0 + i - 1)     & (H - 1)) * W];
            vert[i * VS + t] = s;
        }
    }
    __syncthreads();

    // ---------------- Phase B: horizontal sums via warp scan, direct store ----
    // Warp per row (8 warps x 4 rows). Row data a[c]=vert[r][c], c=0..147.
    // out[x] = P[x+21] - P[x], P = exclusive prefix of a.
    const unsigned FULL = 0xffffffffu;
    const int lane = t & 31;
    const int wp   = t >> 5;

    #pragma unroll
    for (int rr = 0; rr < TY / 8; rr++) {
        const int r = wp * (TY / 8) + rr;
        const float* row = vert + r * VS;

        // lane quad: a[4l .. 4l+3]  (c 0..127), one aligned LDS.128
        float4 q = *reinterpret_cast<const float4*>(row + 4 * lane);
        // extras: a[128..147] on lanes 0..19
        float e = (lane < 20) ? row[128 + lane] : 0.0f;

        const float s1 = q.x;
        const float s2 = s1 + q.y;
        const float s3 = s2 + q.z;
        const float s4 = s3 + q.w;

        // inclusive scan of quad totals -> v; B = P[4*lane]
        float v = s4;
        #pragma unroll
        for (int d = 1; d < 32; d <<= 1) {
            float u = __shfl_up_sync(FULL, v, d);
            if (lane >= d) v += u;
        }
        const float B = v - s4;

        // inclusive scan of extras -> w (w[l] = T[l+1] = sum a[128..128+l])
        float w = e;
        #pragma unroll
        for (int d = 1; d < 32; d <<= 1) {
            float u = __shfl_up_sync(FULL, w, d);
            if (lane >= d) w += u;
        }
        const float P128 = __shfl_sync(FULL, v, 31);   // P[128]

        // P[4l+21+j] from lane l+5 (j=0..2: B'+s_{j+1}; j=3: B'+s4')
        const float Bp  = __shfl_down_sync(FULL, B,  5);
        const float s1p = __shfl_down_sync(FULL, s1, 5);
        const float s2p = __shfl_down_sync(FULL, s2, 5);
        const float s3p = __shfl_down_sync(FULL, s3, 5);
        const float s4p = __shfl_down_sync(FULL, s4, 5);

        // tail (lanes 27..31): P[idx] = P128 + T[idx-128], T[k] at w-lane k-1
        const int base = 4 * (lane - 27);
        const float w0 = __shfl_sync(FULL, w, (base + 0) & 31);
        const float w1 = __shfl_sync(FULL, w, (base + 1) & 31);
        const float w2 = __shfl_sync(FULL, w, (base + 2) & 31);
        const float w3 = __shfl_sync(FULL, w, (base + 3) & 31);

        const bool tail = (lane >= 27);
        const float u0 = tail ? (P128 + w0) : (Bp + s1p);
        const float u1 = tail ? (P128 + w1) : (Bp + s2p);
        const float u2 = tail ? (P128 + w2) : (Bp + s3p);
        const float u3 = tail ? (P128 + w3) : (Bp + s4p);

        float4 o;
        o.x = u0 - B;
        o.y = u1 - (B + s1);
        o.z = u2 - (B + s2);
        o.w = u3 - (B + s3);

        *reinterpret_cast<float4*>(
            outg + (size_t)(tileY + r) * W + tileX + 4 * lane) = o;
    }
}

extern "C" void kernel_launch(void* const* d_in, const int* in_sizes, int n_in,
                              void* d_out, int out_size)
{
    const float* x = (const float*)d_in[0];
    float* out = (float*)d_out;

    dim3 grid(W / TX, H / TY, NB);   // (16, 64, 8) = 8192 blocks
    box_filter_kernel<<<grid, THREADS>>>(x, out);
}